// round 1
// baseline (speedup 1.0000x reference)
#include <cuda_runtime.h>
#include <cuda_bf16.h>
#include <math.h>

#define N_NODES 100000
#define N_EDGES 800000
#define D_DATA  100
#define H_DIM   256
#define N_CLS   47
#define K_STEPS 10

// ---------------- static device scratch (no allocs allowed) ----------------
__device__ float g_buf0[(size_t)N_NODES * D_DATA];   // 40 MB
__device__ float g_buf1[(size_t)N_NODES * D_DATA];   // 40 MB
__device__ int   d_cnt[N_NODES];
__device__ int   d_ptr[N_NODES + 1];
__device__ int   d_cursor[N_NODES];
__device__ float d_norm[N_NODES];
__device__ float d_n2[N_NODES];
__device__ int   d_csr[N_EDGES];

// ---------------- CSR build ----------------
__global__ void zero_cnt_kernel() {
    int i = blockIdx.x * blockDim.x + threadIdx.x;
    if (i < N_NODES) d_cnt[i] = 0;
}

__global__ void count_kernel(const int* __restrict__ dst) {
    int e = blockIdx.x * blockDim.x + threadIdx.x;
    if (e < N_EDGES) atomicAdd(&d_cnt[dst[e]], 1);
}

#define SCAN_T 1024
#define SCAN_CH 98   // ceil(100000/1024)
__global__ void scan_kernel() {
    __shared__ int part[SCAN_T];
    int t = threadIdx.x;
    int beg = t * SCAN_CH;
    int end = beg + SCAN_CH; if (end > N_NODES) end = N_NODES;
    if (beg > N_NODES) beg = N_NODES;
    int s = 0;
    for (int i = beg; i < end; i++) s += d_cnt[i];
    part[t] = s;
    __syncthreads();
    for (int off = 1; off < SCAN_T; off <<= 1) {
        int v = (t >= off) ? part[t - off] : 0;
        __syncthreads();
        part[t] += v;
        __syncthreads();
    }
    int run = part[t] - s;   // exclusive prefix
    for (int i = beg; i < end; i++) {
        d_ptr[i] = run;
        d_cursor[i] = run;
        run += d_cnt[i];
    }
    if (t == SCAN_T - 1) d_ptr[N_NODES] = part[SCAN_T - 1];
}

__global__ void norm_kernel() {
    int i = blockIdx.x * blockDim.x + threadIdx.x;
    if (i < N_NODES) {
        float dg = (float)d_cnt[i];
        float nm = rsqrtf(fmaxf(dg, 1.0f));
        d_norm[i] = nm;
        d_n2[i] = nm * nm;
    }
}

__global__ void fill_kernel(const int* __restrict__ src, const int* __restrict__ dst) {
    int e = blockIdx.x * blockDim.x + threadIdx.x;
    if (e < N_EDGES) {
        int d = dst[e];
        int p = atomicAdd(&d_cursor[d], 1);
        d_csr[p] = src[e];
    }
}

// ---------------- propagation ----------------
// g0 = x * norm
__global__ void init_g_kernel(const float* __restrict__ x) {
    int idx = blockIdx.x * blockDim.x + threadIdx.x;
    if (idx < N_NODES * D_DATA) {
        int node = idx / D_DATA;
        g_buf0[idx] = x[idx] * d_norm[node];
    }
}

// Warp per node. gout = s1 * sum_e gin[src] + s2 * x
// non-last: s1 = 0.9*n2[i], s2 = 0.1*norm[i]   (output stays in g-space)
// last:     s1 = 0.9*norm[i], s2 = 0.1         (output is h)
__global__ void prop_kernel(const float* __restrict__ gin,
                            float* __restrict__ gout,
                            const float* __restrict__ x,
                            int last) {
    int warp = (blockIdx.x * blockDim.x + threadIdx.x) >> 5;
    int lane = threadIdx.x & 31;
    if (warp >= N_NODES) return;
    int beg = d_ptr[warp];
    int end = d_ptr[warp + 1];
    float a0 = 0.f, a1 = 0.f, a2 = 0.f, a3 = 0.f;
    for (int e = beg; e < end; e++) {
        const float* gs = gin + (size_t)d_csr[e] * D_DATA;
        a0 += gs[lane];
        a1 += gs[lane + 32];
        a2 += gs[lane + 64];
        if (lane < 4) a3 += gs[lane + 96];
    }
    float ni = d_norm[warp];
    float s1, s2;
    if (last) { s1 = 0.9f * ni;         s2 = 0.1f; }
    else      { s1 = 0.9f * d_n2[warp]; s2 = 0.1f * ni; }
    const float* xi = x + (size_t)warp * D_DATA;
    float* go = gout + (size_t)warp * D_DATA;
    go[lane]      = s1 * a0 + s2 * xi[lane];
    go[lane + 32] = s1 * a1 + s2 * xi[lane + 32];
    go[lane + 64] = s1 * a2 + s2 * xi[lane + 64];
    if (lane < 4) go[lane + 96] = s1 * a3 + s2 * xi[lane + 96];
}

// ---------------- fused MLP: logits = relu(h@W1+b1)@W2+b2 ----------------
#define TM 32
#define HS_STRIDE 104
#define W2_STRIDE 48
#define MLP_THREADS 256

#define MLP_SMEM_FLOATS (D_DATA*H_DIM + H_DIM*W2_STRIDE + H_DIM + 48 + TM*HS_STRIDE + TM*H_DIM)

__global__ void __launch_bounds__(MLP_THREADS, 1)
mlp_kernel(const float* __restrict__ h,
           const float* __restrict__ W1, const float* __restrict__ b1,
           const float* __restrict__ W2, const float* __restrict__ b2,
           float* __restrict__ out) {
    extern __shared__ float sm[];
    float* W1s = sm;                               // [d][j] 100x256
    float* W2s = W1s + D_DATA * H_DIM;             // [j][c] 256x48 padded
    float* b1s = W2s + H_DIM * W2_STRIDE;
    float* b2s = b1s + H_DIM;
    float* hs  = b2s + 48;                         // [m][104]
    float* zs  = hs + TM * HS_STRIDE;              // [m][256]

    int tid = threadIdx.x;

    for (int i = tid; i < D_DATA * H_DIM; i += MLP_THREADS) W1s[i] = W1[i];
    for (int i = tid; i < H_DIM * W2_STRIDE; i += MLP_THREADS) {
        int j = i / W2_STRIDE, c = i % W2_STRIDE;
        W2s[i] = (c < N_CLS) ? W2[j * N_CLS + c] : 0.f;
    }
    for (int i = tid; i < H_DIM; i += MLP_THREADS) b1s[i] = b1[i];
    if (tid < N_CLS) b2s[tid] = b2[tid];
    __syncthreads();

    int jg = tid & 31, mg = tid >> 5;
    int j0 = jg * 8, m0 = mg * 4;
    int cg2 = tid % 24, mg2 = tid / 24;
    int c0 = cg2 * 2, mm0 = mg2 * 4;

    int n_tiles = (N_NODES + TM - 1) / TM;
    for (int tile = blockIdx.x; tile < n_tiles; tile += gridDim.x) {
        int node0 = tile * TM;

        for (int i = tid; i < TM * D_DATA; i += MLP_THREADS) {
            int m = i / D_DATA, d = i % D_DATA;
            int node = node0 + m;
            hs[m * HS_STRIDE + d] = (node < N_NODES) ? h[(size_t)node * D_DATA + d] : 0.f;
        }
        __syncthreads();

        // phase 1: z = relu(h@W1+b1), 4m x 8j frags
        float acc[4][8];
        #pragma unroll
        for (int mi = 0; mi < 4; mi++)
            #pragma unroll
            for (int ji = 0; ji < 8; ji++) acc[mi][ji] = 0.f;

        #pragma unroll 2
        for (int d = 0; d < D_DATA; d++) {
            const float4 w0 = *(const float4*)(W1s + d * H_DIM + j0);
            const float4 w1 = *(const float4*)(W1s + d * H_DIM + j0 + 4);
            float hv[4];
            #pragma unroll
            for (int mi = 0; mi < 4; mi++) hv[mi] = hs[(m0 + mi) * HS_STRIDE + d];
            #pragma unroll
            for (int mi = 0; mi < 4; mi++) {
                acc[mi][0] = fmaf(hv[mi], w0.x, acc[mi][0]);
                acc[mi][1] = fmaf(hv[mi], w0.y, acc[mi][1]);
                acc[mi][2] = fmaf(hv[mi], w0.z, acc[mi][2]);
                acc[mi][3] = fmaf(hv[mi], w0.w, acc[mi][3]);
                acc[mi][4] = fmaf(hv[mi], w1.x, acc[mi][4]);
                acc[mi][5] = fmaf(hv[mi], w1.y, acc[mi][5]);
                acc[mi][6] = fmaf(hv[mi], w1.z, acc[mi][6]);
                acc[mi][7] = fmaf(hv[mi], w1.w, acc[mi][7]);
            }
        }
        #pragma unroll
        for (int mi = 0; mi < 4; mi++) {
            #pragma unroll
            for (int ji = 0; ji < 8; ji++)
                zs[(m0 + mi) * H_DIM + j0 + ji] = fmaxf(acc[mi][ji] + b1s[j0 + ji], 0.f);
        }
        __syncthreads();

        // phase 2: logits = z@W2 + b2, first 192 threads: 4m x 2c each
        if (tid < 192) {
            float a2[4][2];
            #pragma unroll
            for (int mi = 0; mi < 4; mi++) { a2[mi][0] = 0.f; a2[mi][1] = 0.f; }
            #pragma unroll 4
            for (int j = 0; j < H_DIM; j++) {
                float w0 = W2s[j * W2_STRIDE + c0];
                float w1 = W2s[j * W2_STRIDE + c0 + 1];
                #pragma unroll
                for (int mi = 0; mi < 4; mi++) {
                    float zv = zs[(mm0 + mi) * H_DIM + j];
                    a2[mi][0] = fmaf(zv, w0, a2[mi][0]);
                    a2[mi][1] = fmaf(zv, w1, a2[mi][1]);
                }
            }
            #pragma unroll
            for (int mi = 0; mi < 4; mi++) {
                int node = node0 + mm0 + mi;
                if (node < N_NODES) {
                    #pragma unroll
                    for (int ci = 0; ci < 2; ci++) {
                        int c = c0 + ci;
                        if (c < N_CLS)
                            out[(size_t)node * N_CLS + c] = a2[mi][ci] + b2s[c];
                    }
                }
            }
        }
        __syncthreads();
    }
}

// ---------------- launch ----------------
extern "C" void kernel_launch(void* const* d_in, const int* in_sizes, int n_in,
                              void* d_out, int out_size) {
    const float* x   = (const float*)d_in[0];
    const int*   src = (const int*)d_in[1];
    const int*   dst = (const int*)d_in[2];
    const float* W1  = (const float*)d_in[3];
    const float* b1  = (const float*)d_in[4];
    const float* W2  = (const float*)d_in[5];
    const float* b2  = (const float*)d_in[6];
    float* out = (float*)d_out;

    cudaFuncSetAttribute(mlp_kernel, cudaFuncAttributeMaxDynamicSharedMemorySize,
                         MLP_SMEM_FLOATS * 4);

    float* p0 = nullptr;
    float* p1 = nullptr;
    cudaGetSymbolAddress((void**)&p0, g_buf0);
    cudaGetSymbolAddress((void**)&p1, g_buf1);

    int nb_nodes = (N_NODES + 255) / 256;
    int nb_edges = (N_EDGES + 255) / 256;

    zero_cnt_kernel<<<nb_nodes, 256>>>();
    count_kernel<<<nb_edges, 256>>>(dst);
    scan_kernel<<<1, SCAN_T>>>();
    norm_kernel<<<nb_nodes, 256>>>();
    fill_kernel<<<nb_edges, 256>>>(src, dst);

    int nb_init = (N_NODES * D_DATA + 255) / 256;
    init_g_kernel<<<nb_init, 256>>>(x);

    int nb_prop = (N_NODES * 32 + 255) / 256;   // one warp per node
    for (int t = 0; t < K_STEPS; t++) {
        const float* gin = (t & 1) ? p1 : p0;
        float* gout      = (t & 1) ? p0 : p1;
        prop_kernel<<<nb_prop, 256>>>(gin, gout, x, (t == K_STEPS - 1) ? 1 : 0);
    }
    // after an even number of steps the result lives in g_buf0
    mlp_kernel<<<148, MLP_THREADS, MLP_SMEM_FLOATS * 4>>>(p0, W1, b1, W2, b2, out);
}

// round 2
// speedup vs baseline: 1.0876x; 1.0876x over previous
#include <cuda_runtime.h>
#include <cuda_bf16.h>
#include <math.h>

#define N_NODES 100000
#define N_EDGES 800000
#define D_DATA  100
#define H_DIM   256
#define N_CLS   47
#define K_STEPS 10
#define D_VEC   25          // D_DATA / 4 float4s per row

// ---------------- static device scratch ----------------
__device__ float g_buf0[(size_t)N_NODES * D_DATA];   // 40 MB
__device__ float g_buf1[(size_t)N_NODES * D_DATA];   // 40 MB
__device__ int   d_cnt[N_NODES];
__device__ int   d_ptr[N_NODES + 1];
__device__ int   d_cursor[N_NODES];
__device__ float d_norm[N_NODES];
__device__ float d_n2[N_NODES];
__device__ int   d_csr[N_EDGES];

// ---------------- f32x2 packed helpers ----------------
#define FMA2(acc, a, b) \
    asm("fma.rn.f32x2 %0, %1, %2, %0;" : "+l"(acc) : "l"(a), "l"(b))
#define PACK_DUP(dst, v) \
    asm("mov.b64 %0, {%1, %1};" : "=l"(dst) : "r"(__float_as_uint(v)))
#define UNPACK2(lo, hi, v) \
    asm("mov.b64 {%0, %1}, %2;" : "=f"(lo), "=f"(hi) : "l"(v))

// ---------------- CSR build ----------------
__global__ void zero_cnt_kernel() {
    int i = blockIdx.x * blockDim.x + threadIdx.x;
    if (i < N_NODES) d_cnt[i] = 0;
}

__global__ void count_kernel(const int* __restrict__ dst) {
    int e = blockIdx.x * blockDim.x + threadIdx.x;
    if (e < N_EDGES) atomicAdd(&d_cnt[dst[e]], 1);
}

#define SCAN_T 1024
#define SCAN_CH 98   // ceil(100000/1024)
__global__ void scan_kernel() {
    __shared__ int part[SCAN_T];
    int t = threadIdx.x;
    int beg = t * SCAN_CH;
    int end = beg + SCAN_CH; if (end > N_NODES) end = N_NODES;
    if (beg > N_NODES) beg = N_NODES;
    int s = 0;
    for (int i = beg; i < end; i++) s += d_cnt[i];
    part[t] = s;
    __syncthreads();
    for (int off = 1; off < SCAN_T; off <<= 1) {
        int v = (t >= off) ? part[t - off] : 0;
        __syncthreads();
        part[t] += v;
        __syncthreads();
    }
    int run = part[t] - s;
    for (int i = beg; i < end; i++) {
        d_ptr[i] = run;
        d_cursor[i] = run;
        run += d_cnt[i];
    }
    if (t == SCAN_T - 1) d_ptr[N_NODES] = part[SCAN_T - 1];
}

__global__ void norm_kernel() {
    int i = blockIdx.x * blockDim.x + threadIdx.x;
    if (i < N_NODES) {
        float dg = (float)d_cnt[i];
        float nm = rsqrtf(fmaxf(dg, 1.0f));
        d_norm[i] = nm;
        d_n2[i] = nm * nm;
    }
}

__global__ void fill_kernel(const int* __restrict__ src, const int* __restrict__ dst) {
    int e = blockIdx.x * blockDim.x + threadIdx.x;
    if (e < N_EDGES) {
        int d = dst[e];
        int p = atomicAdd(&d_cursor[d], 1);
        d_csr[p] = src[e];
    }
}

// ---------------- propagation ----------------
// g0 = x * norm   (vectorized: one float4 per thread)
__global__ void init_g_kernel(const float4* __restrict__ x) {
    int idx = blockIdx.x * blockDim.x + threadIdx.x;
    if (idx < N_NODES * D_VEC) {
        int node = idx / D_VEC;
        float nm = d_norm[node];
        float4 v = x[idx];
        v.x *= nm; v.y *= nm; v.z *= nm; v.w *= nm;
        ((float4*)g_buf0)[idx] = v;
    }
}

// Warp per node. Warp-cooperative index load + 1 LDG.128 per edge (25 lanes).
// gout = s1 * sum_e gin[src] + s2 * x
__global__ void prop_kernel(const float4* __restrict__ gin,
                            float4* __restrict__ gout,
                            const float4* __restrict__ x,
                            int last) {
    int warp = (blockIdx.x * blockDim.x + threadIdx.x) >> 5;
    int lane = threadIdx.x & 31;
    if (warp >= N_NODES) return;
    int beg = d_ptr[warp];
    int end = d_ptr[warp + 1];

    float a0 = 0.f, a1 = 0.f, a2 = 0.f, a3 = 0.f;
    bool act = lane < D_VEC;

    for (int base = beg; base < end; base += 32) {
        int n = end - base; if (n > 32) n = 32;
        int idx = (lane < n) ? d_csr[base + lane] : 0;
        #pragma unroll 4
        for (int e = 0; e < n; e++) {
            int s = __shfl_sync(0xffffffffu, idx, e);
            if (act) {
                float4 v = gin[s * D_VEC + lane];
                a0 += v.x; a1 += v.y; a2 += v.z; a3 += v.w;
            }
        }
    }

    float ni = d_norm[warp];
    float s1, s2;
    if (last) { s1 = 0.9f * ni;         s2 = 0.1f; }
    else      { s1 = 0.9f * d_n2[warp]; s2 = 0.1f * ni; }

    if (act) {
        float4 xv = x[warp * D_VEC + lane];
        float4 o;
        o.x = s1 * a0 + s2 * xv.x;
        o.y = s1 * a1 + s2 * xv.y;
        o.z = s1 * a2 + s2 * xv.z;
        o.w = s1 * a3 + s2 * xv.w;
        gout[warp * D_VEC + lane] = o;
    }
}

// ---------------- fused MLP: logits = relu(h@W1+b1)@W2+b2 ----------------
// FFMA2 (fma.rn.f32x2) everywhere.
// Phase 1: 256 threads, per-thread 2m x 16j (8 f32x2 pairs x 4 chunks).
//   W1 staged into smem PERMUTED: 16B unit (d,k,jg) at index (d*4+k)*16+jg
//   so each LDS.128 instruction hits 16 contiguous 16B units -> conflict-free.
// Phase 2: j-paired accumulation. W2 transposed [c][j] stride 258 -> stride-6
//   bank walk across 16 lanes, conflict-free; z pairs contiguous LDS.64.
#define TM 32
#define HS_STRIDE 104
#define W2T_STRIDE 258
#define MLP_THREADS 256

#define SM_W1P  (D_DATA * H_DIM)            // 25600
#define SM_W2T  (48 * W2T_STRIDE)           // 12384
#define SM_B1   (H_DIM)
#define SM_B2   (48)
#define SM_HS   (TM * HS_STRIDE)            // 3328
#define SM_ZS   (TM * H_DIM)                // 8192
#define MLP_SMEM_FLOATS (SM_W1P + SM_W2T + SM_B1 + SM_B2 + SM_HS + SM_ZS)

__global__ void __launch_bounds__(MLP_THREADS, 1)
mlp_kernel(const float* __restrict__ h,
           const float* __restrict__ W1, const float* __restrict__ b1,
           const float* __restrict__ W2, const float* __restrict__ b2,
           float* __restrict__ out) {
    extern __shared__ float sm[];
    float* W1p = sm;                        // permuted, as float4 units
    float* W2t = W1p + SM_W1P;              // [c][j], stride 258
    float* b1s = W2t + SM_W2T;
    float* b2s = b1s + SM_B1;
    float* hs  = b2s + SM_B2;               // [m][104]
    float* zs  = hs + SM_HS;                // [m][256]

    int tid = threadIdx.x;

    // --- stage weights ---
    {
        const float4* W1v = (const float4*)W1;         // 100 x 64 chunks
        float4* W1pv = (float4*)W1p;
        for (int i = tid; i < D_DATA * 64; i += MLP_THREADS) {
            int d = i >> 6, u = i & 63;                // u = src chunk = j/4
            int k = u & 3, jg = u >> 2;
            W1pv[(d * 4 + k) * 16 + jg] = W1v[i];      // coalesced read
        }
    }
    for (int i = tid; i < 48 * H_DIM; i += MLP_THREADS) {
        int c = i >> 8, j = i & 255;
        W2t[c * W2T_STRIDE + j] = (c < N_CLS) ? W2[j * N_CLS + c] : 0.f;
    }
    for (int i = tid; i < H_DIM; i += MLP_THREADS) b1s[i] = b1[i];
    if (tid < 48) b2s[tid] = (tid < N_CLS) ? b2[tid] : 0.f;
    __syncthreads();

    // phase-1 mapping: jg = tid&15 (16 j), mg = tid>>4 (2 m)
    int jg = tid & 15, mg = tid >> 4;
    int j0 = jg * 16, m0 = mg * 2;
    // phase-2 mapping: cg = tid&15 (3 c), mg2 = tid>>4 (2 m)
    int cg = tid & 15, mg2 = tid >> 4;
    int c0 = cg * 3, mm0 = mg2 * 2;

    const ulonglong2* W1q = (const ulonglong2*)W1p;

    int n_tiles = N_NODES / TM;   // 3125 exact
    for (int tile = blockIdx.x; tile < n_tiles; tile += gridDim.x) {
        int node0 = tile * TM;

        for (int i = tid; i < TM * D_DATA; i += MLP_THREADS) {
            int m = i / D_DATA, d = i - m * D_DATA;
            hs[m * HS_STRIDE + d] = h[(size_t)(node0 + m) * D_DATA + d];
        }
        __syncthreads();

        // ---- phase 1: z = relu(h@W1 + b1), packed pairs over j ----
        unsigned long long acc[2][8];
        #pragma unroll
        for (int k = 0; k < 4; k++) {
            unsigned long long blo = *(const unsigned long long*)(b1s + j0 + k * 4);
            unsigned long long bhi = *(const unsigned long long*)(b1s + j0 + k * 4 + 2);
            acc[0][k * 2]     = blo; acc[0][k * 2 + 1] = bhi;
            acc[1][k * 2]     = blo; acc[1][k * 2 + 1] = bhi;
        }

        #pragma unroll 2
        for (int d = 0; d < D_DATA; d++) {
            unsigned long long w[8];
            #pragma unroll
            for (int k = 0; k < 4; k++) {
                ulonglong2 wq = W1q[(d * 4 + k) * 16 + jg];
                w[k * 2] = wq.x; w[k * 2 + 1] = wq.y;
            }
            unsigned long long hv2[2];
            #pragma unroll
            for (int mi = 0; mi < 2; mi++) {
                float hv = hs[(m0 + mi) * HS_STRIDE + d];
                PACK_DUP(hv2[mi], hv);
            }
            #pragma unroll
            for (int mi = 0; mi < 2; mi++)
                #pragma unroll
                for (int p = 0; p < 8; p++)
                    FMA2(acc[mi][p], hv2[mi], w[p]);
        }

        #pragma unroll
        for (int mi = 0; mi < 2; mi++) {
            #pragma unroll
            for (int p = 0; p < 8; p++) {
                float lo, hi;
                UNPACK2(lo, hi, acc[mi][p]);
                int j = j0 + (p >> 1) * 4 + (p & 1) * 2;
                float2 zv = make_float2(fmaxf(lo, 0.f), fmaxf(hi, 0.f));
                *(float2*)(zs + (m0 + mi) * H_DIM + j) = zv;
            }
        }
        __syncthreads();

        // ---- phase 2: logits = z@W2 + b2, j-paired accumulators ----
        unsigned long long a2[2][3];
        #pragma unroll
        for (int mi = 0; mi < 2; mi++)
            #pragma unroll
            for (int ci = 0; ci < 3; ci++) a2[mi][ci] = 0ull;

        #pragma unroll 4
        for (int j2 = 0; j2 < H_DIM / 2; j2++) {
            unsigned long long zz[2], ww[3];
            #pragma unroll
            for (int mi = 0; mi < 2; mi++)
                zz[mi] = *(const unsigned long long*)(zs + (mm0 + mi) * H_DIM + j2 * 2);
            #pragma unroll
            for (int ci = 0; ci < 3; ci++)
                ww[ci] = *(const unsigned long long*)(W2t + (c0 + ci) * W2T_STRIDE + j2 * 2);
            #pragma unroll
            for (int mi = 0; mi < 2; mi++)
                #pragma unroll
                for (int ci = 0; ci < 3; ci++)
                    FMA2(a2[mi][ci], zz[mi], ww[ci]);
        }

        #pragma unroll
        for (int mi = 0; mi < 2; mi++) {
            int node = node0 + mm0 + mi;
            #pragma unroll
            for (int ci = 0; ci < 3; ci++) {
                int c = c0 + ci;
                if (c < N_CLS) {
                    float lo, hi;
                    UNPACK2(lo, hi, a2[mi][ci]);
                    out[(size_t)node * N_CLS + c] = lo + hi + b2s[c];
                }
            }
        }
        __syncthreads();
    }
}

// ---------------- launch ----------------
extern "C" void kernel_launch(void* const* d_in, const int* in_sizes, int n_in,
                              void* d_out, int out_size) {
    const float* x   = (const float*)d_in[0];
    const int*   src = (const int*)d_in[1];
    const int*   dst = (const int*)d_in[2];
    const float* W1  = (const float*)d_in[3];
    const float* b1  = (const float*)d_in[4];
    const float* W2  = (const float*)d_in[5];
    const float* b2  = (const float*)d_in[6];
    float* out = (float*)d_out;

    cudaFuncSetAttribute(mlp_kernel, cudaFuncAttributeMaxDynamicSharedMemorySize,
                         MLP_SMEM_FLOATS * 4);

    float* p0 = nullptr;
    float* p1 = nullptr;
    cudaGetSymbolAddress((void**)&p0, g_buf0);
    cudaGetSymbolAddress((void**)&p1, g_buf1);

    int nb_nodes = (N_NODES + 255) / 256;
    int nb_edges = (N_EDGES + 255) / 256;

    zero_cnt_kernel<<<nb_nodes, 256>>>();
    count_kernel<<<nb_edges, 256>>>(dst);
    scan_kernel<<<1, SCAN_T>>>();
    norm_kernel<<<nb_nodes, 256>>>();
    fill_kernel<<<nb_edges, 256>>>(src, dst);

    int nb_init = (N_NODES * D_VEC + 255) / 256;
    init_g_kernel<<<nb_init, 256>>>((const float4*)x);

    int nb_prop = (N_NODES * 32 + 255) / 256;   // one warp per node
    for (int t = 0; t < K_STEPS; t++) {
        const float* gin = (t & 1) ? p1 : p0;
        float* gout      = (t & 1) ? p0 : p1;
        prop_kernel<<<nb_prop, 256>>>((const float4*)gin, (float4*)gout,
                                      (const float4*)x, (t == K_STEPS - 1) ? 1 : 0);
    }
    // after an even number of steps the result lives in g_buf0
    mlp_kernel<<<152, MLP_THREADS, MLP_SMEM_FLOATS * 4>>>(p0, W1, b1, W2, b2, out);
}